// round 3
// baseline (speedup 1.0000x reference)
#include <cuda_runtime.h>
#include <cstdint>

#define B_TOT  16384
#define G_TOT  128
#define SMAX_D 64
#define H_DIM  10
#define PH_DIM 100

// ---------- packed f32x2 helpers ----------
__device__ __forceinline__ unsigned long long pack2(float lo, float hi) {
    unsigned long long r;
    asm("mov.b64 %0, {%1, %2};" : "=l"(r) : "f"(lo), "f"(hi));
    return r;
}
__device__ __forceinline__ float2 unpack2(unsigned long long v) {
    float2 r;
    asm("mov.b64 {%0, %1}, %2;" : "=f"(r.x), "=f"(r.y) : "l"(v));
    return r;
}
__device__ __forceinline__ void fma2(unsigned long long& d, unsigned long long a, unsigned long long b) {
    asm("fma.rn.f32x2 %0, %1, %2, %0;" : "+l"(d) : "l"(a), "l"(b));
}

// gene_layer scratch, transposed: glT[g][b]  (8.4 MB, static device array — no allocs)
__device__ float g_glT[(size_t)G_TOT * B_TOT];

// ============================================================================
// Stage 1+2: per-gene MLP  ->  gene_layer[b,g]  (stored transposed [g,b])
//   h = relu(x[b,g,:] @ W1[g] + b1[g]);  gl = h . W2[g] + b2[g]
// One block per (gene, batch tile of 1024). 256 threads, NB=4 batches/thread.
// W1 staged in smem pre-paired along S for fma.rn.f32x2.
// ============================================================================
#define T1 256
#define NB 4

__global__ __launch_bounds__(T1)
void gene_mlp_kernel(const float* __restrict__ x,
                     const float* __restrict__ W1,
                     const float* __restrict__ b1,
                     const float* __restrict__ W2,
                     const float* __restrict__ b2)
{
    __shared__ unsigned long long w1p[(SMAX_D / 2) * H_DIM];  // (s,s+1) pairs, 2560B
    __shared__ float b1s[H_DIM];
    __shared__ float W2s[H_DIM];
    __shared__ float b2s;

    const int g   = blockIdx.y;
    const int tid = threadIdx.x;

    // stage W1[g] as S-pairs: w1p[sp*H + h] = (W1[g][2sp][h], W1[g][2sp+1][h])
    for (int i = tid; i < (SMAX_D / 2) * H_DIM; i += T1) {
        int sp = i / H_DIM, h = i % H_DIM;
        const float* base = W1 + ((size_t)g * SMAX_D + 2 * sp) * H_DIM + h;
        w1p[i] = pack2(base[0], base[H_DIM]);
    }
    if (tid < H_DIM) { b1s[tid] = b1[g * H_DIM + tid]; W2s[tid] = W2[g * H_DIM + tid]; }
    if (tid == 0) b2s = b2[g];
    __syncthreads();

    const int bBase = blockIdx.x * (T1 * NB) + tid;

    const float4* xr[NB];
#pragma unroll
    for (int nb = 0; nb < NB; nb++)
        xr[nb] = reinterpret_cast<const float4*>(
            x + ((size_t)(bBase + nb * T1) * G_TOT + g) * SMAX_D);

    unsigned long long acc[NB][H_DIM];
#pragma unroll
    for (int nb = 0; nb < NB; nb++)
#pragma unroll
        for (int h = 0; h < H_DIM; h++) acc[nb][h] = 0ull;

#pragma unroll 4
    for (int s4 = 0; s4 < SMAX_D / 4; s4++) {
        float4 xv[NB];
#pragma unroll
        for (int nb = 0; nb < NB; nb++) xv[nb] = xr[nb][s4];

        unsigned long long xp[NB][2];
#pragma unroll
        for (int nb = 0; nb < NB; nb++) {
            xp[nb][0] = pack2(xv[nb].x, xv[nb].y);
            xp[nb][1] = pack2(xv[nb].z, xv[nb].w);
        }
#pragma unroll
        for (int sp = 0; sp < 2; sp++) {
#pragma unroll
            for (int h = 0; h < H_DIM; h++) {
                unsigned long long w = w1p[(s4 * 2 + sp) * H_DIM + h];  // LDS.64 broadcast
#pragma unroll
                for (int nb = 0; nb < NB; nb++) fma2(acc[nb][h], xp[nb][sp], w);
            }
        }
    }

    // epilogue: collapse pairs, bias, relu, project through W2
#pragma unroll
    for (int nb = 0; nb < NB; nb++) {
        float gacc = b2s;
#pragma unroll
        for (int h = 0; h < H_DIM; h++) {
            float2 v = unpack2(acc[nb][h]);
            float s = fmaxf(v.x + v.y + b1s[h], 0.0f);
            gacc = fmaf(s, W2s[h], gacc);
        }
        g_glT[(size_t)g * B_TOT + (bBase + nb * T1)] = gacc;  // coalesced (consecutive b)
    }
}

// ============================================================================
// Stage 3+4: out[b] = relu(gl[b,:] @ Wp1 + bp1) @ Wp2 + bp2
// Block: 256 threads, 128 batches (2 threads/batch, each owning 50 PH as 25 f32x2).
// gene_layer tile + Wp1 (paired along PH) staged in dynamic smem.
// ============================================================================
#define T2  256
#define BT2 128
#define SMEM2 (G_TOT * BT2 * 4 + G_TOT * (PH_DIM / 2) * 8)  // 64KB + 51.2KB

__global__ __launch_bounds__(T2)
void pred_kernel(const float* __restrict__ Wp1,
                 const float* __restrict__ bp1,
                 const float* __restrict__ Wp2,
                 const float* __restrict__ bp2,
                 float* __restrict__ out)
{
    extern __shared__ unsigned char smem[];
    float* gls = reinterpret_cast<float*>(smem);                                   // [G][BT2]
    unsigned long long* wp1p = reinterpret_cast<unsigned long long*>(smem + G_TOT * BT2 * 4); // [G][50]

    const int tid   = threadIdx.x;
    const int bBase = blockIdx.x * BT2;

    // stage gene_layer tile: glT[g][bBase..bBase+127] — coalesced float4 loads
    {
        const int rowv = BT2 / 4;  // 32 float4 per row
        for (int i4 = tid; i4 < G_TOT * rowv; i4 += T2) {
            int g = i4 / rowv, c4 = i4 % rowv;
            float4 v = *reinterpret_cast<const float4*>(
                g_glT + (size_t)g * B_TOT + bBase + c4 * 4);
            reinterpret_cast<float4*>(gls)[i4] = v;
        }
    }
    // stage Wp1 as PH-pairs (contiguous in memory -> coalesced float2 loads)
    for (int i = tid; i < G_TOT * (PH_DIM / 2); i += T2) {
        float2 v = reinterpret_cast<const float2*>(Wp1)[i];
        wp1p[i] = pack2(v.x, v.y);
    }
    __syncthreads();

    const int bl   = tid >> 1;  // local batch
    const int half = tid & 1;   // which 50 PH outputs

    unsigned long long acc[PH_DIM / 4];  // 25 f32x2
#pragma unroll
    for (int j = 0; j < PH_DIM / 4; j++) acc[j] = 0ull;

    for (int g = 0; g < G_TOT; g++) {
        float glv = gls[g * BT2 + bl];
        unsigned long long glp = pack2(glv, glv);
        const unsigned long long* wrow = wp1p + g * (PH_DIM / 2) + half * (PH_DIM / 4);
#pragma unroll
        for (int j = 0; j < PH_DIM / 4; j++) fma2(acc[j], glp, wrow[j]);
    }

    float part = 0.0f;
#pragma unroll
    for (int j = 0; j < PH_DIM / 4; j++) {
        int ph = half * (PH_DIM / 2) + 2 * j;
        float2 v = unpack2(acc[j]);
        float p0 = fmaxf(v.x + __ldg(bp1 + ph),     0.0f);
        float p1 = fmaxf(v.y + __ldg(bp1 + ph + 1), 0.0f);
        part = fmaf(p0, __ldg(Wp2 + ph),     part);
        part = fmaf(p1, __ldg(Wp2 + ph + 1), part);
    }
    part += __shfl_xor_sync(0xffffffffu, part, 1);
    if (half == 0) out[bBase + bl] = part + __ldg(bp2);
}

// ============================================================================
extern "C" void kernel_launch(void* const* d_in, const int* in_sizes, int n_in,
                              void* d_out, int out_size)
{
    (void)in_sizes; (void)n_in; (void)out_size;
    const float* x   = (const float*)d_in[0];
    const float* W1  = (const float*)d_in[1];
    const float* b1  = (const float*)d_in[2];
    const float* W2  = (const float*)d_in[3];
    const float* b2  = (const float*)d_in[4];
    const float* Wp1 = (const float*)d_in[5];
    const float* bp1 = (const float*)d_in[6];
    const float* Wp2 = (const float*)d_in[7];
    const float* bp2 = (const float*)d_in[8];
    float* out = (float*)d_out;

    cudaFuncSetAttribute(pred_kernel, cudaFuncAttributeMaxDynamicSharedMemorySize, SMEM2);

    dim3 grid1(B_TOT / (T1 * NB), G_TOT);  // (16, 128)
    gene_mlp_kernel<<<grid1, T1>>>(x, W1, b1, W2, b2);

    pred_kernel<<<B_TOT / BT2, T2, SMEM2>>>(Wp1, bp1, Wp2, bp2, out);
}

// round 12
// speedup vs baseline: 1.5497x; 1.5497x over previous
#include <cuda_runtime.h>
#include <cstdint>

#define B_TOT  16384
#define G_TOT  128
#define SMAX_D 64
#define H_DIM  10
#define PH_DIM 100

// ---------- packed f32x2 helpers ----------
__device__ __forceinline__ unsigned long long pack2(float lo, float hi) {
    unsigned long long r;
    asm("mov.b64 %0, {%1, %2};" : "=l"(r) : "f"(lo), "f"(hi));
    return r;
}
__device__ __forceinline__ float2 unpack2(unsigned long long v) {
    float2 r;
    asm("mov.b64 {%0, %1}, %2;" : "=f"(r.x), "=f"(r.y) : "l"(v));
    return r;
}
__device__ __forceinline__ void fma2(unsigned long long& d, unsigned long long a, unsigned long long b) {
    asm("fma.rn.f32x2 %0, %1, %2, %0;" : "+l"(d) : "l"(a), "l"(b));
}

// ragged per-gene SNP counts: GENE_DIMS = tile([4,8,12,16,24,32,48,64], 16) -> g % 8
__constant__ int c_mdims[8] = {4, 8, 12, 16, 24, 32, 48, 64};

// gene_layer scratch, transposed: glT[g][b]  (8.4 MB static device array)
__device__ float g_glT[(size_t)G_TOT * B_TOT];

// ============================================================================
// Stage 1+2: per-gene MLP -> gene_layer (stored transposed [g,b])
// Block = (gene g, tile of BT=256 batches), T1=128 threads, NB=2 batches/thread.
// x tile staged in dynamic smem with coalesced loads; only first m_g SNPs
// touched (padded region of x and W1 is exactly zero).
// W1 staged as S-pairs, h-pairs read via LDS.128.
// ============================================================================
#define T1 128
#define NB 2
#define BT (T1 * NB)          // 256
#define W1ROW 12              // padded row of ull pairs (10 used), 16B-aligned rows
#define XS_MAX_FLOATS (BT * (SMAX_D + 4))   // worst case stride 68
#define XS_SMEM_BYTES (XS_MAX_FLOATS * 4)   // 69632

__global__ __launch_bounds__(T1)
void gene_mlp_kernel(const float* __restrict__ x,
                     const float* __restrict__ W1,
                     const float* __restrict__ b1,
                     const float* __restrict__ W2,
                     const float* __restrict__ b2)
{
    extern __shared__ float xs[];                       // [BT][stride]
    __shared__ unsigned long long w1p[(SMAX_D / 2) * W1ROW];
    __shared__ float b1s[H_DIM], W2s[H_DIM];
    __shared__ float b2s;

    const int g   = blockIdx.y;
    const int tid = threadIdx.x;
    const int m   = c_mdims[g & 7];                     // real SNP count for this gene
    // bank-conflict-free row stride: stride % 8 == 4 (all m are mult of 4)
    const int stride = m + (((m & 7) == 0) ? 4 : 0);
    const int nv = m >> 2;                              // float4 per used row

    // stage W1[g] as S-pairs: w1p[sp*W1ROW + h] = (W1[g][2sp][h], W1[g][2sp+1][h])
    for (int i = tid; i < (m / 2) * H_DIM; i += T1) {
        int sp = i / H_DIM, h = i - sp * H_DIM;
        const float* base = W1 + ((size_t)g * SMAX_D + 2 * sp) * H_DIM + h;
        w1p[sp * W1ROW + h] = pack2(base[0], base[H_DIM]);
    }
    if (tid < H_DIM) { b1s[tid] = b1[g * H_DIM + tid]; W2s[tid] = W2[g * H_DIM + tid]; }
    if (tid == 0) b2s = b2[g];

    // stage x tile: rows bBase..bBase+BT-1, first m floats each — coalesced
    const int bBase = blockIdx.x * BT;
    const float4* x4 = reinterpret_cast<const float4*>(x);
    const size_t rowStride4 = (size_t)G_TOT * SMAX_D / 4;   // float4 units per batch
    const size_t gOff4 = (size_t)g * (SMAX_D / 4);
    for (int idx = tid; idx < BT * nv; idx += T1) {
        int r = idx / nv, c = idx - r * nv;
        float4 v = x4[(size_t)(bBase + r) * rowStride4 + gOff4 + c];
        *reinterpret_cast<float4*>(&xs[r * stride + c * 4]) = v;
    }
    __syncthreads();

    // compute: thread owns rows tid and tid+T1
    unsigned long long acc[NB][H_DIM];
#pragma unroll
    for (int nb = 0; nb < NB; nb++)
#pragma unroll
        for (int h = 0; h < H_DIM; h++) acc[nb][h] = 0ull;

    const float4* xr0 = reinterpret_cast<const float4*>(&xs[tid * stride]);
    const float4* xr1 = reinterpret_cast<const float4*>(&xs[(tid + T1) * stride]);

    for (int s4 = 0; s4 < nv; s4++) {
        float4 xa = xr0[s4];
        float4 xb = xr1[s4];
        unsigned long long xp[NB][2];
        xp[0][0] = pack2(xa.x, xa.y); xp[0][1] = pack2(xa.z, xa.w);
        xp[1][0] = pack2(xb.x, xb.y); xp[1][1] = pack2(xb.z, xb.w);
#pragma unroll
        for (int sp = 0; sp < 2; sp++) {
            const int spi = s4 * 2 + sp;
#pragma unroll
            for (int h2 = 0; h2 < 5; h2++) {
                // LDS.128: two adjacent h weight-pairs (rows 96B apart -> 16B aligned)
                ulonglong2 w2 = *reinterpret_cast<const ulonglong2*>(&w1p[spi * W1ROW + h2 * 2]);
#pragma unroll
                for (int nb = 0; nb < NB; nb++) {
                    fma2(acc[nb][h2 * 2 + 0], xp[nb][sp], w2.x);
                    fma2(acc[nb][h2 * 2 + 1], xp[nb][sp], w2.y);
                }
            }
        }
    }

    // epilogue: collapse pairs, bias, relu, project through W2; coalesced store
#pragma unroll
    for (int nb = 0; nb < NB; nb++) {
        float gacc = b2s;
#pragma unroll
        for (int h = 0; h < H_DIM; h++) {
            float2 v = unpack2(acc[nb][h]);
            float s = fmaxf(v.x + v.y + b1s[h], 0.0f);
            gacc = fmaf(s, W2s[h], gacc);
        }
        g_glT[(size_t)g * B_TOT + (bBase + nb * T1 + tid)] = gacc;
    }
}

// ============================================================================
// Stage 3+4: out[b] = relu(gl[b,:] @ Wp1 + bp1) @ Wp2 + bp2
// T2=128 threads, BT2=128 batches/block: thread (half, bl) owns batches
// {bl, bl+64} and PH half [half*50, half*50+50) as 25 f32x2 accumulators.
// gls stored [g][bl] (lane-contiguous), Wp1 pairs warp-uniform broadcast.
// ============================================================================
#define T2  128
#define BT2 128
#define PRED_SMEM (G_TOT * BT2 * 4 + G_TOT * (PH_DIM / 2) * 8 + 2 * 64 * 4)

__global__ __launch_bounds__(T2)
void pred_kernel(const float* __restrict__ Wp1,
                 const float* __restrict__ bp1,
                 const float* __restrict__ Wp2,
                 const float* __restrict__ bp2,
                 float* __restrict__ out)
{
    extern __shared__ unsigned char smem[];
    float* gls = reinterpret_cast<float*>(smem);                                    // [G][BT2]
    unsigned long long* wp1p =
        reinterpret_cast<unsigned long long*>(smem + G_TOT * BT2 * 4);              // [G][50]
    float* parts = reinterpret_cast<float*>(smem + G_TOT * BT2 * 4 + G_TOT * 50 * 8); // [2][64]

    const int tid   = threadIdx.x;
    const int bBase = blockIdx.x * BT2;

    // stage gene_layer tile [g][bl] — coalesced float4 from glT[g][bBase+...]
    for (int i4 = tid; i4 < G_TOT * (BT2 / 4); i4 += T2) {
        int g = i4 / (BT2 / 4), c4 = i4 - g * (BT2 / 4);
        float4 v = *reinterpret_cast<const float4*>(g_glT + (size_t)g * B_TOT + bBase + c4 * 4);
        *reinterpret_cast<float4*>(&gls[g * BT2 + c4 * 4]) = v;
    }
    // stage Wp1 as PH-pairs (bit-identical 8B copies, coalesced)
    for (int i = tid; i < G_TOT * (PH_DIM / 2); i += T2) {
        wp1p[i] = reinterpret_cast<const unsigned long long*>(Wp1)[i];
    }
    __syncthreads();

    const int half = tid >> 6;          // warp-uniform (warps 0-1: half 0, warps 2-3: half 1)
    const int bl   = tid & 63;

    unsigned long long acc0[PH_DIM / 4], acc1[PH_DIM / 4];   // 25 + 25 f32x2
#pragma unroll
    for (int j = 0; j < PH_DIM / 4; j++) { acc0[j] = 0ull; acc1[j] = 0ull; }

    for (int g = 0; g < G_TOT; g++) {
        float ga = gls[g * BT2 + bl];            // lane-contiguous, conflict-free
        float gb = gls[g * BT2 + bl + 64];
        unsigned long long pa = pack2(ga, ga);
        unsigned long long pb = pack2(gb, gb);
        const unsigned long long* wrow = wp1p + g * (PH_DIM / 2) + half * (PH_DIM / 4);
#pragma unroll
        for (int j = 0; j < PH_DIM / 4; j++) {
            unsigned long long w = wrow[j];      // warp-uniform broadcast
            fma2(acc0[j], pa, w);
            fma2(acc1[j], pb, w);
        }
    }

    float p0 = 0.0f, p1 = 0.0f;
#pragma unroll
    for (int j = 0; j < PH_DIM / 4; j++) {
        int ph = half * (PH_DIM / 2) + 2 * j;
        float bA = __ldg(bp1 + ph), bB = __ldg(bp1 + ph + 1);
        float wA = __ldg(Wp2 + ph), wB = __ldg(Wp2 + ph + 1);
        float2 v0 = unpack2(acc0[j]);
        float2 v1 = unpack2(acc1[j]);
        p0 = fmaf(fmaxf(v0.x + bA, 0.0f), wA, p0);
        p0 = fmaf(fmaxf(v0.y + bB, 0.0f), wB, p0);
        p1 = fmaf(fmaxf(v1.x + bA, 0.0f), wA, p1);
        p1 = fmaf(fmaxf(v1.y + bB, 0.0f), wB, p1);
    }

    // combine the two PH halves (held by threads in different warps) via smem
    if (half == 1) { parts[bl] = p0; parts[64 + bl] = p1; }
    __syncthreads();
    if (half == 0) {
        float bias = __ldg(bp2);
        out[bBase + bl]      = p0 + parts[bl]      + bias;
        out[bBase + bl + 64] = p1 + parts[64 + bl] + bias;
    }
}

// ============================================================================
extern "C" void kernel_launch(void* const* d_in, const int* in_sizes, int n_in,
                              void* d_out, int out_size)
{
    (void)in_sizes; (void)n_in; (void)out_size;
    const float* x   = (const float*)d_in[0];
    const float* W1  = (const float*)d_in[1];
    const float* b1  = (const float*)d_in[2];
    const float* W2  = (const float*)d_in[3];
    const float* b2  = (const float*)d_in[4];
    const float* Wp1 = (const float*)d_in[5];
    const float* bp1 = (const float*)d_in[6];
    const float* Wp2 = (const float*)d_in[7];
    const float* bp2 = (const float*)d_in[8];
    float* out = (float*)d_out;

    cudaFuncSetAttribute(gene_mlp_kernel, cudaFuncAttributeMaxDynamicSharedMemorySize, XS_SMEM_BYTES);
    cudaFuncSetAttribute(pred_kernel,     cudaFuncAttributeMaxDynamicSharedMemorySize, PRED_SMEM);

    dim3 grid1(B_TOT / BT, G_TOT);   // (64, 128)
    gene_mlp_kernel<<<grid1, T1, XS_SMEM_BYTES>>>(x, W1, b1, W2, b2);

    pred_kernel<<<B_TOT / BT2, T2, PRED_SMEM>>>(Wp1, bp1, Wp2, bp2, out);
}